// round 7
// baseline (speedup 1.0000x reference)
#include <cuda_runtime.h>
#include <cuda_bf16.h>
#include <stdint.h>

// ---------------------------------------------------------------------------
// Problem constants
// ---------------------------------------------------------------------------
#define NPTS  128
#define W     1024
#define L     1024
#define MTOT  2048          // 2 channels * W
#define SIGMA 32.0f

// bf16 split GEMM: K' = 3*128  (Ah*Bh + Al*Bh + Ah*Bl; dropped Al*Bl ~ 2^-18)
#define KP   384
#define NKS  (KP / 16)      // 24 k-steps of 16
#define BM   128
#define BN   128
#define NSTG 4              // cp.async pipeline stages

// ---------------------------------------------------------------------------
// Fragment-layout scratch tables (__device__ globals; no allocation).
// Laid out PER K-STEP so each CTA's per-kstep slice is one contiguous 4 KB
// block (coalesced cp.async fill):
//   gAf2[ks][mt(128)][lane(32)][reg(4)][half(2)]  bf16  (16 B per lane)
//   gBf2[ks][nt(128)][lane(32)][reg(2)][half(2)]  bf16  ( 8 B per lane)
// ---------------------------------------------------------------------------
__device__ __align__(16) __nv_bfloat16 gAf2[NKS * (MTOT / 16) * 32 * 8]; // 1.5 MB
__device__ __align__(16) __nv_bfloat16 gBf2[NKS * (L / 8)    * 32 * 4]; // 768 KB

// mma.sync m16n8k16 .row.col fragment index math (PTX ISA layouts)
__device__ __forceinline__ void storeA(int m, int k, __nv_bfloat16 v) {
    const int mt = m >> 4, rm = m & 15;
    const int ks = k >> 4, rk = k & 15;
    const int lane = (rm & 7) * 4 + ((rk & 7) >> 1);
    const int reg  = (rm >> 3) + ((rk >> 3) << 1);
    const int half = rk & 1;
    gAf2[(((ks * (MTOT / 16) + mt) * 32 + lane) * 4 + reg) * 2 + half] = v;
}
__device__ __forceinline__ void storeB(int y, int k, __nv_bfloat16 v) {
    const int nt = y >> 3;
    const int ks = k >> 4, rk = k & 15;
    const int lane = (y & 7) * 4 + ((rk & 7) >> 1);
    const int reg  = rk >> 3;
    const int half = rk & 1;
    gBf2[(((ks * (L / 8) + nt) * 32 + lane) * 2 + reg) * 2 + half] = v;
}

// ---------------------------------------------------------------------------
// Kernel 1: separable tables with bf16 hi/lo split, fragment layout.
// grid = 1024 (coordinate i), block = 128 (point n)
// coords are int32 (JAX x64 disabled downcasts jnp.int64 -> int32)
// ---------------------------------------------------------------------------
__global__ void precompute_kernel(const float* __restrict__ vecs,
                                  const int* __restrict__ xc,
                                  const int* __restrict__ yc)
{
    const int i = blockIdx.x;      // coordinate 0..1023
    const int n = threadIdx.x;     // point 0..127
    const float inv2s2 = 1.0f / (2.0f * SIGMA * SIGMA);

    const float fi = (float)i;
    const float dx = fi - (float)xc[n];
    const float dy = fi - (float)yc[n];
    const float ex = __expf(-dx * dx * inv2s2);
    const float ey = __expf(-dy * dy * inv2s2);

    const float a0 = ex * vecs[n];          // channel 0
    const float a1 = ex * vecs[NPTS + n];   // channel 1

    const __nv_bfloat16 a0h = __float2bfloat16(a0);
    const __nv_bfloat16 a0l = __float2bfloat16(a0 - __bfloat162float(a0h));
    const __nv_bfloat16 a1h = __float2bfloat16(a1);
    const __nv_bfloat16 a1l = __float2bfloat16(a1 - __bfloat162float(a1h));
    const __nv_bfloat16 bh  = __float2bfloat16(ey);
    const __nv_bfloat16 bl  = __float2bfloat16(ey - __bfloat162float(bh));

    // A rows: ch0 -> m = i, ch1 -> m = W + i. K blocks: [Ah | Al | Ah]
    storeA(i,     n,       a0h);
    storeA(i,     128 + n, a0l);
    storeA(i,     256 + n, a0h);
    storeA(W + i, n,       a1h);
    storeA(W + i, 128 + n, a1l);
    storeA(W + i, 256 + n, a1h);
    // B row y = i. K blocks: [Bh | Bh | Bl]
    storeB(i, n,       bh);
    storeB(i, 128 + n, bh);
    storeB(i, 256 + n, bl);
}

// ---------------------------------------------------------------------------
// Kernel 2: HMMA GEMM with cp.async 4-stage smem pipeline.
// CTA tile 128x128, 256 threads = 8 warps in 4(m) x 2(n); warp tile 32x64.
// ---------------------------------------------------------------------------
__device__ __forceinline__ void mma16816(float* c, const uint32_t* a,
                                         const uint32_t* b) {
    asm volatile(
        "mma.sync.aligned.m16n8k16.row.col.f32.bf16.bf16.f32 "
        "{%0,%1,%2,%3}, {%4,%5,%6,%7}, {%8,%9}, {%0,%1,%2,%3};"
        : "+f"(c[0]), "+f"(c[1]), "+f"(c[2]), "+f"(c[3])
        : "r"(a[0]), "r"(a[1]), "r"(a[2]), "r"(a[3]),
          "r"(b[0]), "r"(b[1]));
}
__device__ __forceinline__ uint32_t smem_u32(const void* p) {
    uint32_t a;
    asm("{ .reg .u64 t; cvta.to.shared.u64 t, %1; cvt.u32.u64 %0, t; }"
        : "=r"(a) : "l"(p));
    return a;
}
__device__ __forceinline__ void cp16(uint32_t dst, const void* src) {
    asm volatile("cp.async.cg.shared.global [%0], [%1], 16;"
                 :: "r"(dst), "l"(src));
}
#define CP_COMMIT() asm volatile("cp.async.commit_group;" ::: "memory")
#define CP_WAIT2()  asm volatile("cp.async.wait_group 2;"  ::: "memory")

__global__ void __launch_bounds__(256, 1)
gemm_mma_kernel(float* __restrict__ out)
{
    __shared__ __align__(16) char sA[NSTG * 4096];
    __shared__ __align__(16) char sB[NSTG * 4096];

    const int tid  = threadIdx.x;
    const int wid  = tid >> 5;
    const int lane = tid & 31;

    const int y_base = blockIdx.x * BN;     // 8 blocks
    const int m_base = blockIdx.y * BM;     // 16 blocks

    const int wm = wid >> 1;                // 0..3 (m dir, 32 rows)
    const int wn = wid & 1;                 // 0..1 (n dir, 64 cols)

    const uint32_t sa_base = smem_u32(sA);
    const uint32_t sb_base = smem_u32(sB);

    // Per-CTA contiguous 4 KB global slices per k-step
    const char* gA = (const char*)gAf2 + (size_t)(m_base / 16) * 512;
    const char* gB = (const char*)gBf2 + (size_t)(y_base / 8)  * 256;
    // k-step stride in bytes: A: 128 mt * 512 B; B: 128 nt * 256 B
    const size_t A_KS = (size_t)(MTOT / 16) * 512;   // 65536
    const size_t B_KS = (size_t)(L / 8) * 256;       // 32768

    // prologue: fill stages 0..NSTG-2
#pragma unroll
    for (int s = 0; s < NSTG - 1; s++) {
        cp16(sa_base + s * 4096 + tid * 16, gA + (size_t)s * A_KS + tid * 16);
        cp16(sb_base + s * 4096 + tid * 16, gB + (size_t)s * B_KS + tid * 16);
        CP_COMMIT();
    }

    float acc[2][8][4] = {};                // [im][in][creg]

    const uint32_t a_off = wm * 1024 + lane * 16;       // 2 mt x 512 B
    const uint32_t b_off = wn * 2048 + lane * 8;        // 8 nt x 256 B

#pragma unroll 4
    for (int ks = 0; ks < NKS; ks++) {
        CP_WAIT2();
        __syncthreads();

        const int stg = ks & (NSTG - 1);
        uint4 a[2];
        uint2 b[8];
#pragma unroll
        for (int im = 0; im < 2; im++)
            a[im] = *(const uint4*)(sA + stg * 4096 + a_off + im * 512);
#pragma unroll
        for (int in = 0; in < 8; in++)
            b[in] = *(const uint2*)(sB + stg * 4096 + b_off + in * 256);

        // issue next fill (overlaps with MMAs)
        const int nks = ks + NSTG - 1;
        if (nks < NKS) {
            const int ns = nks & (NSTG - 1);
            cp16(sa_base + ns * 4096 + tid * 16, gA + (size_t)nks * A_KS + tid * 16);
            cp16(sb_base + ns * 4096 + tid * 16, gB + (size_t)nks * B_KS + tid * 16);
        }
        CP_COMMIT();   // empty group at tail keeps wait_group accounting valid

#pragma unroll
        for (int im = 0; im < 2; im++)
#pragma unroll
            for (int in = 0; in < 8; in++)
                mma16816(acc[im][in], (const uint32_t*)&a[im],
                         (const uint32_t*)&b[in]);
    }

    // Epilogue: c0,c1 = (row g, cols 2t,2t+1); c2,c3 = (row g+8)
    const int g = lane >> 2;
    const int t = lane & 3;
#pragma unroll
    for (int im = 0; im < 2; im++) {
        const int row0 = m_base + wm * 32 + im * 16 + g;
#pragma unroll
        for (int in = 0; in < 8; in++) {
            const int col = y_base + wn * 64 + in * 8 + t * 2;
            float2* p0 = (float2*)(out + (size_t)row0 * L + col);
            float2* p1 = (float2*)(out + (size_t)(row0 + 8) * L + col);
            *p0 = make_float2(acc[im][in][0], acc[im][in][1]);
            *p1 = make_float2(acc[im][in][2], acc[im][in][3]);
        }
    }
}

// ---------------------------------------------------------------------------
extern "C" void kernel_launch(void* const* d_in, const int* in_sizes, int n_in,
                              void* d_out, int out_size)
{
    const float* vecs = (const float*)d_in[0];   // [2,128] fp32
    const int*   xc   = (const int*)d_in[1];     // [128] int32
    const int*   yc   = (const int*)d_in[2];     // [128] int32
    float* out = (float*)d_out;                  // [1,2,1024,1024] fp32

    (void)in_sizes; (void)n_in; (void)out_size;

    precompute_kernel<<<1024, 128>>>(vecs, xc, yc);

    dim3 grid(L / BN, MTOT / BM);   // (8, 16) = 128 CTAs, one wave
    gemm_mma_kernel<<<grid, 256>>>(out);
}

// round 9
// speedup vs baseline: 1.0383x; 1.0383x over previous
#include <cuda_runtime.h>
#include <cuda_bf16.h>
#include <stdint.h>

// ---------------------------------------------------------------------------
// Problem constants
// ---------------------------------------------------------------------------
#define NPTS  128
#define W     1024
#define L     1024
#define MTOT  2048          // 2 channels * W
#define SIGMA 32.0f

// Logical GEMM K' = 384 = [Ah|Al|Ah] x [Bh|Bh|Bl]  (dropped Al*Bl ~ 2^-18)
// Physical storage: A = [Ah|Al] (16 k-steps), B = [Bh|Bl] (16 k-steps)
#define NKS_LOG  24
#define NKS_PHYS 16
#define BM 128
#define BN 128

// ---------------------------------------------------------------------------
// Physical fragment tables (__device__ globals; no allocation).
//   gAp[ksp(16)][mt(128)][lane(32)][reg(4)][half(2)]  bf16  -> 1 MB
//   gBp[ksp(16)][nt(128)][lane(32)][reg(2)][half(2)]  bf16  -> 512 KB
// ksp 0-7 = hi part, ksp 8-15 = lo part (A: Al, B: Bl)
// ---------------------------------------------------------------------------
__device__ __align__(16) __nv_bfloat16 gAp[NKS_PHYS * (MTOT / 16) * 32 * 8];
__device__ __align__(16) __nv_bfloat16 gBp[NKS_PHYS * (L / 8) * 32 * 4];

// ---------------------------------------------------------------------------
// Kernel 1: build fragment tables, one thread per fragment word (coalesced).
// grid 512 x 256: blocks [0,256) -> A (uint4/thread), [256,512) -> B (uint2).
// coords are int32 (JAX x64 disabled downcasts jnp.int64 -> int32)
//
// mma.sync m16n8k16 .row.col fragment layout (PTX ISA):
//   A slot(reg,half): rm = (lane>>2)+8*(reg&1); rk = (reg>>1)*8+(lane&3)*2+half
//   B slot(reg,half): y_in = lane>>2;           rk = reg*8+(lane&3)*2+half
// ---------------------------------------------------------------------------
__global__ void precompute_kernel(const float* __restrict__ vecs,
                                  const int* __restrict__ xc,
                                  const int* __restrict__ yc)
{
    const float inv2s2 = 1.0f / (2.0f * SIGMA * SIGMA);
    const int bid = blockIdx.x;

    if (bid < 256) {
        // ---- A fragments ----
        const int gid  = bid * 256 + threadIdx.x;        // 0..65535
        const int lane = gid & 31;
        const int mt   = (gid >> 5) & 127;
        const int ksp  = gid >> 12;                       // 0..15
        const bool hi  = (ksp < 8);

        union { uint4 u; __nv_bfloat16 v[8]; } pack;
#pragma unroll
        for (int reg = 0; reg < 4; reg++) {
#pragma unroll
            for (int half = 0; half < 2; half++) {
                const int rm = (lane >> 2) + 8 * (reg & 1);
                const int rk = ((reg >> 1) << 3) + ((lane & 3) << 1) + half;
                const int m  = mt * 16 + rm;
                const int n  = (ksp * 16 + rk) & 127;    // point index
                const int x  = m & 1023;
                const int c  = m >> 10;
                const float dx = (float)x - (float)xc[n];
                const float a  = __expf(-dx * dx * inv2s2) * vecs[c * NPTS + n];
                const __nv_bfloat16 ah = __float2bfloat16(a);
                pack.v[reg * 2 + half] =
                    hi ? ah : __float2bfloat16(a - __bfloat162float(ah));
            }
        }
        ((uint4*)gAp)[gid] = pack.u;
    } else {
        // ---- B fragments ----
        const int gid  = (bid - 256) * 256 + threadIdx.x; // 0..65535
        const int lane = gid & 31;
        const int nt   = (gid >> 5) & 127;
        const int ksp  = gid >> 12;
        const bool hi  = (ksp < 8);

        const int y = nt * 8 + (lane >> 2);
        union { uint2 u; __nv_bfloat16 v[4]; } pack;
#pragma unroll
        for (int reg = 0; reg < 2; reg++) {
#pragma unroll
            for (int half = 0; half < 2; half++) {
                const int rk = (reg << 3) + ((lane & 3) << 1) + half;
                const int n  = (ksp * 16 + rk) & 127;
                const float dy = (float)y - (float)yc[n];
                const float e  = __expf(-dy * dy * inv2s2);
                const __nv_bfloat16 bh = __float2bfloat16(e);
                pack.v[reg * 2 + half] =
                    hi ? bh : __float2bfloat16(e - __bfloat162float(bh));
            }
        }
        ((uint2*)gBp)[gid] = pack.u;
    }
}

// ---------------------------------------------------------------------------
// Kernel 2: HMMA GEMM, whole-K smem resident (128 KB), 3 barriers total.
// CTA tile 128x128, 256 threads = 8 warps in 4(m) x 2(n); warp tile 32x64.
// ---------------------------------------------------------------------------
__device__ __forceinline__ void mma16816(float* c, const uint32_t* a,
                                         const uint32_t* b) {
    asm volatile(
        "mma.sync.aligned.m16n8k16.row.col.f32.bf16.bf16.f32 "
        "{%0,%1,%2,%3}, {%4,%5,%6,%7}, {%8,%9}, {%0,%1,%2,%3};"
        : "+f"(c[0]), "+f"(c[1]), "+f"(c[2]), "+f"(c[3])
        : "r"(a[0]), "r"(a[1]), "r"(a[2]), "r"(a[3]),
          "r"(b[0]), "r"(b[1]));
}
__device__ __forceinline__ uint32_t smem_u32(const void* p) {
    uint32_t a;
    asm("{ .reg .u64 t; cvta.to.shared.u64 t, %1; cvt.u32.u64 %0, t; }"
        : "=r"(a) : "l"(p));
    return a;
}
__device__ __forceinline__ void cp16(uint32_t dst, const void* src) {
    asm volatile("cp.async.cg.shared.global [%0], [%1], 16;"
                 :: "r"(dst), "l"(src));
}
#define CP_COMMIT() asm volatile("cp.async.commit_group;" ::: "memory")

#define SMEM_BYTES (NKS_PHYS * 4096 * 2)   // 128 KB: A stages then B stages

extern __shared__ char smem_dyn[];

__global__ void __launch_bounds__(256, 1)
gemm_mma_kernel(float* __restrict__ out)
{
    char* sA = smem_dyn;                       // 16 stages x 4 KB
    char* sB = smem_dyn + NKS_PHYS * 4096;     // 16 stages x 4 KB

    const int tid  = threadIdx.x;
    const int wid  = tid >> 5;
    const int lane = tid & 31;

    const int y_base = blockIdx.x * BN;        // 8 blocks
    const int m_base = blockIdx.y * BM;        // 16 blocks

    const int wm = wid >> 1;                   // 0..3 (m dir, 32 rows)
    const int wn = wid & 1;                    // 0..1 (n dir, 64 cols)

    const uint32_t sa_base = smem_u32(sA);
    const uint32_t sb_base = smem_u32(sB);

    // Per-CTA contiguous 4 KB global slices per physical k-step
    const char* gA = (const char*)gAp + (size_t)(m_base / 16) * 512;
    const char* gB = (const char*)gBp + (size_t)(y_base / 8) * 256;
    const size_t A_KS = (size_t)(MTOT / 16) * 512;   // 65536 B
    const size_t B_KS = (size_t)(L / 8) * 256;       // 32768 B

    // Issue ALL 16 stage fills up front (one commit group per phys k-step)
#pragma unroll
    for (int s = 0; s < NKS_PHYS; s++) {
        cp16(sa_base + s * 4096 + tid * 16, gA + (size_t)s * A_KS + tid * 16);
        cp16(sb_base + s * 4096 + tid * 16, gB + (size_t)s * B_KS + tid * 16);
        CP_COMMIT();
    }

    float acc[2][8][4] = {};                   // [im][in][creg]

    const uint32_t a_off = wm * 1024 + lane * 16;   // 2 mt x 512 B
    const uint32_t b_off = wn * 2048 + lane * 8;    // 8 nt x 256 B

    // 24 logical k-steps in 4 chunks of 6; barriers only at chunk heads.
#pragma unroll
    for (int Lk = 0; Lk < NKS_LOG; Lk++) {
        if (Lk == 0) {
            asm volatile("cp.async.wait_group 10;" ::: "memory"); // groups 0-5 done
            __syncthreads();
        } else if (Lk == 6) {
            asm volatile("cp.async.wait_group 4;" ::: "memory");  // groups 0-11 done
            __syncthreads();
        } else if (Lk == 12) {
            asm volatile("cp.async.wait_group 0;" ::: "memory");  // all done
            __syncthreads();
        }

        const int ap = (Lk < 16) ? Lk : Lk - 16;   // [Ah|Al|Ah]
        const int bp = (Lk < 8)  ? Lk : Lk - 8;    // [Bh|Bh|Bl]

        uint4 a[2];
        uint2 b[8];
#pragma unroll
        for (int im = 0; im < 2; im++)
            a[im] = *(const uint4*)(sA + ap * 4096 + a_off + im * 512);
#pragma unroll
        for (int in = 0; in < 8; in++)
            b[in] = *(const uint2*)(sB + bp * 4096 + b_off + in * 256);

#pragma unroll
        for (int im = 0; im < 2; im++)
#pragma unroll
            for (int in = 0; in < 8; in++)
                mma16816(acc[im][in], (const uint32_t*)&a[im],
                         (const uint32_t*)&b[in]);
    }

    // Epilogue: c0,c1 = (row g, cols 2t,2t+1); c2,c3 = (row g+8)
    const int g = lane >> 2;
    const int t = lane & 3;
#pragma unroll
    for (int im = 0; im < 2; im++) {
        const int row0 = m_base + wm * 32 + im * 16 + g;
#pragma unroll
        for (int in = 0; in < 8; in++) {
            const int col = y_base + wn * 64 + in * 8 + t * 2;
            float2* p0 = (float2*)(out + (size_t)row0 * L + col);
            float2* p1 = (float2*)(out + (size_t)(row0 + 8) * L + col);
            *p0 = make_float2(acc[im][in][0], acc[im][in][1]);
            *p1 = make_float2(acc[im][in][2], acc[im][in][3]);
        }
    }
}

// ---------------------------------------------------------------------------
extern "C" void kernel_launch(void* const* d_in, const int* in_sizes, int n_in,
                              void* d_out, int out_size)
{
    const float* vecs = (const float*)d_in[0];   // [2,128] fp32
    const int*   xc   = (const int*)d_in[1];     // [128] int32
    const int*   yc   = (const int*)d_in[2];     // [128] int32
    float* out = (float*)d_out;                  // [1,2,1024,1024] fp32

    (void)in_sizes; (void)n_in; (void)out_size;

    precompute_kernel<<<512, 256>>>(vecs, xc, yc);

    cudaFuncSetAttribute(gemm_mma_kernel,
                         cudaFuncAttributeMaxDynamicSharedMemorySize,
                         SMEM_BYTES);
    dim3 grid(L / BN, MTOT / BM);   // (8, 16) = 128 CTAs, one wave
    gemm_mma_kernel<<<grid, 256, SMEM_BYTES>>>(out);
}